// round 9
// baseline (speedup 1.0000x reference)
#include <cuda_runtime.h>
#include <cstdint>

#define N_NODES   100000
#define F_IN      65
#define F_HID     64
#define F_OUT     64
#define MAX_EDGES 1600000
#define NCHUNKS   ((N_NODES + 255) / 256)   // 391

// ---- scratch (same 32.4MB footprint that passed in R7) ---------------------
__device__ __align__(16) float g_y[(size_t)N_NODES * F_HID];  // y = x @ W1
__device__ int g_srcs[MAX_EDGES];    // CSR: src indices grouped by dst
__device__ int g_cnt[N_NODES];       // counts -> excl prefix -> incl end
__device__ int g_bsum[NCHUNKS];      // per-chunk sums for scan
__device__ int g_idx_is64;

// ---------------------------------------------------------------------------
// Kernel 1: zero counts + reset dtype flag.
// ---------------------------------------------------------------------------
__global__ void zero_cnt_kernel() {
    int i = blockIdx.x * blockDim.x + threadIdx.x;
    if (i == 0) g_idx_is64 = 1;
    if (i < N_NODES) g_cnt[i] = 0;
}

// ---------------------------------------------------------------------------
// Kernel 2: sampled dtype probe. If the buffer holds int32 pairs, a fused
// int64 view is out of [0,N_NODES) unless the high word is 0 (p=1e-5/pair);
// 32K+ samples decide with certainty. Fail-safe default: int64.
// ---------------------------------------------------------------------------
__global__ void detect_dtype_kernel(const long long* __restrict__ ei, int n64) {
    int i = blockIdx.x * blockDim.x + threadIdx.x;
    bool bad = false;
    if (i < n64) {
        long long v = ei[i];
        bad = (v < 0) | (v >= N_NODES);
    }
    if (__syncthreads_or(bad) && threadIdx.x == 0) g_idx_is64 = 0;
}

// ---------------------------------------------------------------------------
// Kernel 3: GEMM1  y = x @ W1  (R5-proven: 64x64 tile, 4x4 regs, shared W).
// ---------------------------------------------------------------------------
__global__ void gemm1_kernel(const float* __restrict__ x,
                             const float* __restrict__ W1,
                             int n) {
    __shared__ float shA[64 * 68];                     // [r][k], stride 68
    __shared__ __align__(16) float shW[F_IN * F_HID];  // [k][j]

    int tid  = threadIdx.x;
    int row0 = blockIdx.x * 64;

    for (int t = tid; t < 64 * F_IN; t += 256) {
        int r = t / F_IN;
        int c = t - r * F_IN;
        int row = row0 + r;
        shA[r * 68 + c] = (row < n) ? x[(size_t)row * F_IN + c] : 0.f;
    }
    for (int t = tid; t < F_IN * F_HID; t += 256) shW[t] = W1[t];
    __syncthreads();

    int ty = tid >> 4;
    int tx = tid & 15;

    float acc[4][4];
    #pragma unroll
    for (int i = 0; i < 4; i++)
        #pragma unroll
        for (int j = 0; j < 4; j++) acc[i][j] = 0.f;

    const float* ar = &shA[(ty * 4) * 68];
    #pragma unroll 5
    for (int k = 0; k < F_IN; k++) {
        float a0 = ar[0 * 68 + k];
        float a1 = ar[1 * 68 + k];
        float a2 = ar[2 * 68 + k];
        float a3 = ar[3 * 68 + k];
        float4 b = *reinterpret_cast<const float4*>(&shW[k * F_HID + tx * 4]);
        acc[0][0] = fmaf(a0, b.x, acc[0][0]); acc[0][1] = fmaf(a0, b.y, acc[0][1]);
        acc[0][2] = fmaf(a0, b.z, acc[0][2]); acc[0][3] = fmaf(a0, b.w, acc[0][3]);
        acc[1][0] = fmaf(a1, b.x, acc[1][0]); acc[1][1] = fmaf(a1, b.y, acc[1][1]);
        acc[1][2] = fmaf(a1, b.z, acc[1][2]); acc[1][3] = fmaf(a1, b.w, acc[1][3]);
        acc[2][0] = fmaf(a2, b.x, acc[2][0]); acc[2][1] = fmaf(a2, b.y, acc[2][1]);
        acc[2][2] = fmaf(a2, b.z, acc[2][2]); acc[2][3] = fmaf(a2, b.w, acc[2][3]);
        acc[3][0] = fmaf(a3, b.x, acc[3][0]); acc[3][1] = fmaf(a3, b.y, acc[3][1]);
        acc[3][2] = fmaf(a3, b.z, acc[3][2]); acc[3][3] = fmaf(a3, b.w, acc[3][3]);
    }

    #pragma unroll
    for (int i = 0; i < 4; i++) {
        int row = row0 + ty * 4 + i;
        if (row < n) {
            float4 o = make_float4(acc[i][0], acc[i][1], acc[i][2], acc[i][3]);
            *reinterpret_cast<float4*>(&g_y[(size_t)row * F_HID + tx * 4]) = o;
        }
    }
}

// ---------------------------------------------------------------------------
// Kernel 4: histogram of dst — 4 edges/thread, vectorized index loads.
// ---------------------------------------------------------------------------
__global__ void hist_kernel(const void* __restrict__ edge_index,
                            int n_edges, int n_groups) {
    int g = blockIdx.x * blockDim.x + threadIdx.x;
    if (g >= n_groups) return;
    int e0 = g * 4;
    int m  = n_edges - e0; if (m > 4) m = 4;

    int dst[4];
    if (g_idx_is64) {
        const long long* p = (const long long*)edge_index + n_edges;
        if (m == 4 && (n_edges & 1) == 0) {
            longlong2 d0 = *reinterpret_cast<const longlong2*>(p + e0);
            longlong2 d1 = *reinterpret_cast<const longlong2*>(p + e0 + 2);
            dst[0] = (int)d0.x; dst[1] = (int)d0.y;
            dst[2] = (int)d1.x; dst[3] = (int)d1.y;
        } else {
            for (int i = 0; i < m; i++) dst[i] = (int)p[e0 + i];
        }
    } else {
        const int* p = (const int*)edge_index + n_edges;
        if (m == 4 && (n_edges & 3) == 0) {
            int4 d = *reinterpret_cast<const int4*>(p + e0);
            dst[0] = d.x; dst[1] = d.y; dst[2] = d.z; dst[3] = d.w;
        } else {
            for (int i = 0; i < m; i++) dst[i] = p[e0 + i];
        }
    }
    #pragma unroll
    for (int i = 0; i < 4; i++)
        if (i < m) atomicAdd(&g_cnt[dst[i]], 1);
}

// ---------------------------------------------------------------------------
// Kernels 5a/5b/5c: 3-level exclusive prefix scan of g_cnt (in place).
// ---------------------------------------------------------------------------
__global__ void chunk_sums_kernel() {
    __shared__ int s[256];
    int b = blockIdx.x, t = threadIdx.x;
    int i = b * 256 + t;
    s[t] = (i < N_NODES) ? g_cnt[i] : 0;
    __syncthreads();
    #pragma unroll
    for (int off = 128; off > 0; off >>= 1) {
        if (t < off) s[t] += s[t + off];
        __syncthreads();
    }
    if (t == 0) g_bsum[b] = s[0];
}

__global__ void scan_bsums_kernel() {
    __shared__ int s[512];
    int t = threadIdx.x;
    int v = (t < NCHUNKS) ? g_bsum[t] : 0;
    s[t] = v;
    __syncthreads();
    #pragma unroll
    for (int off = 1; off < 512; off <<= 1) {
        int add = (t >= off) ? s[t - off] : 0;
        __syncthreads();
        s[t] += add;
        __syncthreads();
    }
    if (t < NCHUNKS) g_bsum[t] = s[t] - v;   // exclusive
}

__global__ void scan_chunks_kernel() {
    __shared__ int s[256];
    int b = blockIdx.x, t = threadIdx.x;
    int i = b * 256 + t;
    int v = (i < N_NODES) ? g_cnt[i] : 0;
    s[t] = v;
    __syncthreads();
    #pragma unroll
    for (int off = 1; off < 256; off <<= 1) {
        int add = (t >= off) ? s[t - off] : 0;
        __syncthreads();
        s[t] += add;
        __syncthreads();
    }
    if (i < N_NODES) g_cnt[i] = g_bsum[b] + s[t] - v;   // exclusive prefix
}

// ---------------------------------------------------------------------------
// Kernel 6: fill CSR — 4 edges/thread, vectorized index loads.
// After this, g_cnt[d] = inclusive end offset of node d.
// ---------------------------------------------------------------------------
__global__ void fill_kernel(const void* __restrict__ edge_index,
                            int n_edges, int n_groups) {
    int g = blockIdx.x * blockDim.x + threadIdx.x;
    if (g >= n_groups) return;
    int e0 = g * 4;
    int m  = n_edges - e0; if (m > 4) m = 4;

    int src[4], dst[4];
    if (g_idx_is64) {
        const long long* p = (const long long*)edge_index;
        if (m == 4) {
            longlong2 s0 = *reinterpret_cast<const longlong2*>(p + e0);
            longlong2 s1 = *reinterpret_cast<const longlong2*>(p + e0 + 2);
            src[0] = (int)s0.x; src[1] = (int)s0.y;
            src[2] = (int)s1.x; src[3] = (int)s1.y;
            if ((n_edges & 1) == 0) {
                longlong2 d0 = *reinterpret_cast<const longlong2*>(p + n_edges + e0);
                longlong2 d1 = *reinterpret_cast<const longlong2*>(p + n_edges + e0 + 2);
                dst[0] = (int)d0.x; dst[1] = (int)d0.y;
                dst[2] = (int)d1.x; dst[3] = (int)d1.y;
            } else {
                #pragma unroll
                for (int i = 0; i < 4; i++) dst[i] = (int)p[(size_t)n_edges + e0 + i];
            }
        } else {
            for (int i = 0; i < m; i++) {
                src[i] = (int)p[e0 + i];
                dst[i] = (int)p[(size_t)n_edges + e0 + i];
            }
        }
    } else {
        const int* p = (const int*)edge_index;
        if (m == 4) {
            int4 s = *reinterpret_cast<const int4*>(p + e0);
            src[0] = s.x; src[1] = s.y; src[2] = s.z; src[3] = s.w;
            if ((n_edges & 3) == 0) {
                int4 d = *reinterpret_cast<const int4*>(p + n_edges + e0);
                dst[0] = d.x; dst[1] = d.y; dst[2] = d.z; dst[3] = d.w;
            } else {
                #pragma unroll
                for (int i = 0; i < 4; i++) dst[i] = p[n_edges + e0 + i];
            }
        } else {
            for (int i = 0; i < m; i++) {
                src[i] = p[e0 + i];
                dst[i] = p[n_edges + e0 + i];
            }
        }
    }
    #pragma unroll
    for (int i = 0; i < 4; i++)
        if (i < m) {
            int pos = atomicAdd(&g_cnt[dst[i]], 1);
            g_srcs[pos] = src[i];
        }
}

// ---------------------------------------------------------------------------
// Kernel 7: FUSED aggregate + GEMM2.  Per 64-row block:
//   phase 1: 16 lane-groups accumulate A = relu(y + sum y[src] + b1) into
//            shared (register accumulation, 4-way unrolled gathers)
//   phase 2: R5-proven 64x64 GEMM:  out = A @ W2 + b2   (in-place on d_out)
// ---------------------------------------------------------------------------
__global__ void agg_gemm2_kernel(const float* __restrict__ W2,
                                 const float* __restrict__ b1,
                                 const float* __restrict__ b2,
                                 float* __restrict__ out,
                                 int n) {
    __shared__ __align__(16) float shA[64 * 68];        // [r][k], stride 68
    __shared__ __align__(16) float shW[F_HID * F_OUT];  // [k][j]
    __shared__ float sb2[F_OUT];

    int tid  = threadIdx.x;
    int row0 = blockIdx.x * 64;

    for (int t = tid; t < F_HID * F_OUT; t += 256) shW[t] = W2[t];
    if (tid < F_OUT) sb2[tid] = b2[tid];

    // ---- phase 1: aggregation into shared A-tile ----
    int grp = tid >> 4;          // 0..15
    int q   = tid & 15;          // quad within row
    float4 bv = __ldg(reinterpret_cast<const float4*>(&b1[q * 4]));

    for (int r = grp; r < 64; r += 16) {
        int node = row0 + r;
        float4 v = make_float4(0.f, 0.f, 0.f, 0.f);
        if (node < n) {
            float4 yv = *reinterpret_cast<const float4*>(&g_y[(size_t)node * F_HID + q * 4]);
            v.x = yv.x + bv.x; v.y = yv.y + bv.y;
            v.z = yv.z + bv.z; v.w = yv.w + bv.w;

            int start = node ? g_cnt[node - 1] : 0;
            int end   = g_cnt[node];
            int e = start;
            for (; e + 4 <= end; e += 4) {
                int s0 = g_srcs[e + 0];
                int s1 = g_srcs[e + 1];
                int s2 = g_srcs[e + 2];
                int s3 = g_srcs[e + 3];
                float4 a = *reinterpret_cast<const float4*>(&g_y[(size_t)s0 * F_HID + q * 4]);
                float4 b = *reinterpret_cast<const float4*>(&g_y[(size_t)s1 * F_HID + q * 4]);
                float4 c = *reinterpret_cast<const float4*>(&g_y[(size_t)s2 * F_HID + q * 4]);
                float4 d = *reinterpret_cast<const float4*>(&g_y[(size_t)s3 * F_HID + q * 4]);
                v.x += (a.x + b.x) + (c.x + d.x);
                v.y += (a.y + b.y) + (c.y + d.y);
                v.z += (a.z + b.z) + (c.z + d.z);
                v.w += (a.w + b.w) + (c.w + d.w);
            }
            for (; e < end; e++) {
                int s = g_srcs[e];
                float4 a = *reinterpret_cast<const float4*>(&g_y[(size_t)s * F_HID + q * 4]);
                v.x += a.x; v.y += a.y; v.z += a.z; v.w += a.w;
            }
            v.x = fmaxf(v.x, 0.f); v.y = fmaxf(v.y, 0.f);
            v.z = fmaxf(v.z, 0.f); v.w = fmaxf(v.w, 0.f);
        }
        *reinterpret_cast<float4*>(&shA[r * 68 + q * 4]) = v;
    }
    __syncthreads();

    // ---- phase 2: GEMM ----
    int ty = tid >> 4;
    int tx = tid & 15;

    float acc[4][4];
    {
        float4 b = *reinterpret_cast<const float4*>(&sb2[tx * 4]);
        #pragma unroll
        for (int i = 0; i < 4; i++) {
            acc[i][0] = b.x; acc[i][1] = b.y; acc[i][2] = b.z; acc[i][3] = b.w;
        }
    }

    const float* ar = &shA[(ty * 4) * 68];
    #pragma unroll 8
    for (int k = 0; k < F_HID; k++) {
        float a0 = ar[0 * 68 + k];
        float a1 = ar[1 * 68 + k];
        float a2 = ar[2 * 68 + k];
        float a3 = ar[3 * 68 + k];
        float4 b = *reinterpret_cast<const float4*>(&shW[k * F_OUT + tx * 4]);
        acc[0][0] = fmaf(a0, b.x, acc[0][0]); acc[0][1] = fmaf(a0, b.y, acc[0][1]);
        acc[0][2] = fmaf(a0, b.z, acc[0][2]); acc[0][3] = fmaf(a0, b.w, acc[0][3]);
        acc[1][0] = fmaf(a1, b.x, acc[1][0]); acc[1][1] = fmaf(a1, b.y, acc[1][1]);
        acc[1][2] = fmaf(a1, b.z, acc[1][2]); acc[1][3] = fmaf(a1, b.w, acc[1][3]);
        acc[2][0] = fmaf(a2, b.x, acc[2][0]); acc[2][1] = fmaf(a2, b.y, acc[2][1]);
        acc[2][2] = fmaf(a2, b.z, acc[2][2]); acc[2][3] = fmaf(a2, b.w, acc[2][3]);
        acc[3][0] = fmaf(a3, b.x, acc[3][0]); acc[3][1] = fmaf(a3, b.y, acc[3][1]);
        acc[3][2] = fmaf(a3, b.z, acc[3][2]); acc[3][3] = fmaf(a3, b.w, acc[3][3]);
    }

    #pragma unroll
    for (int i = 0; i < 4; i++) {
        int row = row0 + ty * 4 + i;
        if (row < n) {
            float4 o = make_float4(acc[i][0], acc[i][1], acc[i][2], acc[i][3]);
            *reinterpret_cast<float4*>(&out[(size_t)row * F_OUT + tx * 4]) = o;
        }
    }
}

// ---------------------------------------------------------------------------
extern "C" void kernel_launch(void* const* d_in, const int* in_sizes, int n_in,
                              void* d_out, int out_size) {
    const float* x  = (const float*)d_in[0];   // [100000, 65]
    const void*  ei = d_in[1];                 // [2, E] int64 or int32 (probed)
    const float* W1 = (const float*)d_in[2];   // [65, 64]
    const float* b1 = (const float*)d_in[3];   // [64]
    const float* W2 = (const float*)d_in[4];   // [64, 64]
    const float* b2 = (const float*)d_in[5];   // [64]
    float*       out = (float*)d_out;          // [100000, 64]

    int n_elems = in_sizes[1];
    int n_edges = n_elems / 2;
    if (n_edges > MAX_EDGES) n_edges = MAX_EDGES;

    // 1) zero counts + flag reset
    zero_cnt_kernel<<<(N_NODES + 255) / 256, 256>>>();

    // 2) sampled dtype probe (up to 64K int64 views)
    int nprobe = n_elems / 2;
    if (nprobe > 65536) nprobe = 65536;
    detect_dtype_kernel<<<(nprobe + 255) / 256, 256>>>((const long long*)ei, nprobe);

    // 3) y = x @ W1
    int nblk = (N_NODES + 63) / 64;
    gemm1_kernel<<<nblk, 256>>>(x, W1, N_NODES);

    // 4) CSR build: histogram -> exclusive scan -> fill (4 edges/thread)
    int n_groups = (n_edges + 3) / 4;
    int gblk = (n_groups + 255) / 256;
    hist_kernel<<<gblk, 256>>>(ei, n_edges, n_groups);
    chunk_sums_kernel<<<NCHUNKS, 256>>>();
    scan_bsums_kernel<<<1, 512>>>();
    scan_chunks_kernel<<<NCHUNKS, 256>>>();
    fill_kernel<<<gblk, 256>>>(ei, n_edges, n_groups);

    // 5) fused aggregate + GEMM2 (in-place on d_out)
    agg_gemm2_kernel<<<nblk, 256>>>(W2, b1, b2, out, N_NODES);
}

// round 11
// speedup vs baseline: 1.0647x; 1.0647x over previous
#include <cuda_runtime.h>
#include <cstdint>

#define N_NODES   100000
#define F_IN      65
#define F_HID     64
#define F_OUT     64
#define MAX_EDGES 1600000
#define NCHUNKS   ((N_NODES + 255) / 256)   // 391

// ---- scratch (32.4MB; same footprint proven in R7/R9) ----------------------
__device__ __align__(16) float g_y[(size_t)N_NODES * F_HID];  // y = x @ W1
__device__ int g_srcs[MAX_EDGES];    // CSR: src indices grouped by dst
__device__ int g_cnt[N_NODES];       // counts -> excl prefix -> incl end
__device__ int g_bsum[NCHUNKS];      // per-chunk sums for scan
__device__ int g_idx_is64;

// ---------------------------------------------------------------------------
// Kernel 1: zero counts + reset dtype flag.
// ---------------------------------------------------------------------------
__global__ void zero_cnt_kernel() {
    int i = blockIdx.x * blockDim.x + threadIdx.x;
    if (i == 0) g_idx_is64 = 1;
    if (i < N_NODES) g_cnt[i] = 0;
}

// ---------------------------------------------------------------------------
// Kernel 2: sampled dtype probe (64K int64 views decide with certainty;
// fail-safe default int64).
// ---------------------------------------------------------------------------
__global__ void detect_dtype_kernel(const long long* __restrict__ ei, int n64) {
    int i = blockIdx.x * blockDim.x + threadIdx.x;
    bool bad = false;
    if (i < n64) {
        long long v = ei[i];
        bad = (v < 0) | (v >= N_NODES);
    }
    if (__syncthreads_or(bad) && threadIdx.x == 0) g_idx_is64 = 0;
}

// ---------------------------------------------------------------------------
// Kernel 3: GEMM1  y = x @ W1  (R5-proven: 64x64 tile, 4x4 regs, shared W).
// ---------------------------------------------------------------------------
__global__ void gemm1_kernel(const float* __restrict__ x,
                             const float* __restrict__ W1,
                             int n) {
    __shared__ float shA[64 * 68];                     // [r][k], stride 68
    __shared__ __align__(16) float shW[F_IN * F_HID];  // [k][j]

    int tid  = threadIdx.x;
    int row0 = blockIdx.x * 64;

    for (int t = tid; t < 64 * F_IN; t += 256) {
        int r = t / F_IN;
        int c = t - r * F_IN;
        int row = row0 + r;
        shA[r * 68 + c] = (row < n) ? x[(size_t)row * F_IN + c] : 0.f;
    }
    for (int t = tid; t < F_IN * F_HID; t += 256) shW[t] = W1[t];
    __syncthreads();

    int ty = tid >> 4;
    int tx = tid & 15;

    float acc[4][4];
    #pragma unroll
    for (int i = 0; i < 4; i++)
        #pragma unroll
        for (int j = 0; j < 4; j++) acc[i][j] = 0.f;

    const float* ar = &shA[(ty * 4) * 68];
    #pragma unroll 5
    for (int k = 0; k < F_IN; k++) {
        float a0 = ar[0 * 68 + k];
        float a1 = ar[1 * 68 + k];
        float a2 = ar[2 * 68 + k];
        float a3 = ar[3 * 68 + k];
        float4 b = *reinterpret_cast<const float4*>(&shW[k * F_HID + tx * 4]);
        acc[0][0] = fmaf(a0, b.x, acc[0][0]); acc[0][1] = fmaf(a0, b.y, acc[0][1]);
        acc[0][2] = fmaf(a0, b.z, acc[0][2]); acc[0][3] = fmaf(a0, b.w, acc[0][3]);
        acc[1][0] = fmaf(a1, b.x, acc[1][0]); acc[1][1] = fmaf(a1, b.y, acc[1][1]);
        acc[1][2] = fmaf(a1, b.z, acc[1][2]); acc[1][3] = fmaf(a1, b.w, acc[1][3]);
        acc[2][0] = fmaf(a2, b.x, acc[2][0]); acc[2][1] = fmaf(a2, b.y, acc[2][1]);
        acc[2][2] = fmaf(a2, b.z, acc[2][2]); acc[2][3] = fmaf(a2, b.w, acc[2][3]);
        acc[3][0] = fmaf(a3, b.x, acc[3][0]); acc[3][1] = fmaf(a3, b.y, acc[3][1]);
        acc[3][2] = fmaf(a3, b.z, acc[3][2]); acc[3][3] = fmaf(a3, b.w, acc[3][3]);
    }

    #pragma unroll
    for (int i = 0; i < 4; i++) {
        int row = row0 + ty * 4 + i;
        if (row < n) {
            float4 o = make_float4(acc[i][0], acc[i][1], acc[i][2], acc[i][3]);
            *reinterpret_cast<float4*>(&g_y[(size_t)row * F_HID + tx * 4]) = o;
        }
    }
}

// ---------------------------------------------------------------------------
// Kernel 4: histogram of dst (R7-proven 1-edge/thread).
// ---------------------------------------------------------------------------
__global__ void hist_kernel(const void* __restrict__ edge_index, int n_edges) {
    int e = blockIdx.x * blockDim.x + threadIdx.x;
    if (e >= n_edges) return;
    int dst;
    if (g_idx_is64) dst = (int)((const long long*)edge_index)[(size_t)n_edges + e];
    else            dst = ((const int*)edge_index)[n_edges + e];
    atomicAdd(&g_cnt[dst], 1);
}

// ---------------------------------------------------------------------------
// Kernels 5a/5b/5c: 3-level exclusive prefix scan of g_cnt (in place).
// ---------------------------------------------------------------------------
__global__ void chunk_sums_kernel() {
    __shared__ int s[256];
    int b = blockIdx.x, t = threadIdx.x;
    int i = b * 256 + t;
    s[t] = (i < N_NODES) ? g_cnt[i] : 0;
    __syncthreads();
    #pragma unroll
    for (int off = 128; off > 0; off >>= 1) {
        if (t < off) s[t] += s[t + off];
        __syncthreads();
    }
    if (t == 0) g_bsum[b] = s[0];
}

__global__ void scan_bsums_kernel() {
    __shared__ int s[512];
    int t = threadIdx.x;
    int v = (t < NCHUNKS) ? g_bsum[t] : 0;
    s[t] = v;
    __syncthreads();
    #pragma unroll
    for (int off = 1; off < 512; off <<= 1) {
        int add = (t >= off) ? s[t - off] : 0;
        __syncthreads();
        s[t] += add;
        __syncthreads();
    }
    if (t < NCHUNKS) g_bsum[t] = s[t] - v;   // exclusive
}

__global__ void scan_chunks_kernel() {
    __shared__ int s[256];
    int b = blockIdx.x, t = threadIdx.x;
    int i = b * 256 + t;
    int v = (i < N_NODES) ? g_cnt[i] : 0;
    s[t] = v;
    __syncthreads();
    #pragma unroll
    for (int off = 1; off < 256; off <<= 1) {
        int add = (t >= off) ? s[t - off] : 0;
        __syncthreads();
        s[t] += add;
        __syncthreads();
    }
    if (i < N_NODES) g_cnt[i] = g_bsum[b] + s[t] - v;   // exclusive prefix
}

// ---------------------------------------------------------------------------
// Kernel 6: fill CSR (R7-proven 1-edge/thread).
// After this, g_cnt[d] = inclusive end offset of node d.
// ---------------------------------------------------------------------------
__global__ void fill_kernel(const void* __restrict__ edge_index, int n_edges) {
    int e = blockIdx.x * blockDim.x + threadIdx.x;
    if (e >= n_edges) return;
    int src, dst;
    if (g_idx_is64) {
        const long long* p = (const long long*)edge_index;
        src = (int)p[e];
        dst = (int)p[(size_t)n_edges + e];
    } else {
        const int* p = (const int*)edge_index;
        src = p[e];
        dst = p[n_edges + e];
    }
    int pos = atomicAdd(&g_cnt[dst], 1);
    g_srcs[pos] = src;
}

// ---------------------------------------------------------------------------
// Kernel 7: aggregation with fused epilogue input prep:
//   out[node] = relu( y[node] + b1 + sum_{src in-edges} y[src] )
// 16-lane group per node, 8-way unrolled independent gathers (MLP=8).
// Writes every row -> gemm2 reads only d_out.
// ---------------------------------------------------------------------------
__global__ void aggregate_kernel(const float* __restrict__ b1,
                                 float* __restrict__ out, int n_nodes) {
    int gid = blockIdx.x * (blockDim.x >> 4) + (threadIdx.x >> 4);
    int q   = threadIdx.x & 15;
    if (gid >= n_nodes) return;

    float4 bv = __ldg(reinterpret_cast<const float4*>(&b1[q * 4]));
    float4 yv = *reinterpret_cast<const float4*>(&g_y[(size_t)gid * F_HID + q * 4]);
    float4 v = make_float4(yv.x + bv.x, yv.y + bv.y, yv.z + bv.z, yv.w + bv.w);

    int start = gid ? g_cnt[gid - 1] : 0;
    int end   = g_cnt[gid];

    int e = start;
    for (; e + 8 <= end; e += 8) {
        int s[8];
        #pragma unroll
        for (int i = 0; i < 8; i++) s[i] = g_srcs[e + i];
        float4 a[8];
        #pragma unroll
        for (int i = 0; i < 8; i++)
            a[i] = *reinterpret_cast<const float4*>(&g_y[(size_t)s[i] * F_HID + q * 4]);
        #pragma unroll
        for (int i = 0; i < 8; i++) {
            v.x += a[i].x; v.y += a[i].y; v.z += a[i].z; v.w += a[i].w;
        }
    }
    for (; e < end; e++) {
        int s = g_srcs[e];
        float4 a = *reinterpret_cast<const float4*>(&g_y[(size_t)s * F_HID + q * 4]);
        v.x += a.x; v.y += a.y; v.z += a.z; v.w += a.w;
    }

    v.x = fmaxf(v.x, 0.f); v.y = fmaxf(v.y, 0.f);
    v.z = fmaxf(v.z, 0.f); v.w = fmaxf(v.w, 0.f);
    *reinterpret_cast<float4*>(&out[(size_t)gid * F_HID + q * 4]) = v;
}

// ---------------------------------------------------------------------------
// Kernel 8: GEMM2 (in-place on d_out): out = A @ W2 + b2, A = d_out rows.
// R5-proven 64x64 / 4x4 config; A is ready-made (relu already applied).
// ---------------------------------------------------------------------------
__global__ void gemm2_kernel(const float* __restrict__ W2,
                             const float* __restrict__ b2,
                             float* __restrict__ out,
                             int n) {
    __shared__ __align__(16) float shA[64 * 68];
    __shared__ __align__(16) float shW[F_HID * F_OUT];
    __shared__ float sb2[F_OUT];

    int tid  = threadIdx.x;
    int row0 = blockIdx.x * 64;

    for (int t = tid; t < F_HID * F_OUT; t += 256) shW[t] = W2[t];
    if (tid < F_OUT) sb2[tid] = b2[tid];

    for (int t = tid; t < 64 * 16; t += 256) {
        int r = t >> 4;
        int q = t & 15;
        int row = row0 + r;
        float4 o = make_float4(0.f, 0.f, 0.f, 0.f);
        if (row < n)
            o = *reinterpret_cast<const float4*>(&out[(size_t)row * F_HID + q * 4]);
        *reinterpret_cast<float4*>(&shA[r * 68 + q * 4]) = o;
    }
    __syncthreads();

    int ty = tid >> 4;
    int tx = tid & 15;

    float acc[4][4];
    {
        float4 b = *reinterpret_cast<const float4*>(&sb2[tx * 4]);
        #pragma unroll
        for (int i = 0; i < 4; i++) {
            acc[i][0] = b.x; acc[i][1] = b.y; acc[i][2] = b.z; acc[i][3] = b.w;
        }
    }

    const float* ar = &shA[(ty * 4) * 68];
    #pragma unroll 8
    for (int k = 0; k < F_HID; k++) {
        float a0 = ar[0 * 68 + k];
        float a1 = ar[1 * 68 + k];
        float a2 = ar[2 * 68 + k];
        float a3 = ar[3 * 68 + k];
        float4 b = *reinterpret_cast<const float4*>(&shW[k * F_OUT + tx * 4]);
        acc[0][0] = fmaf(a0, b.x, acc[0][0]); acc[0][1] = fmaf(a0, b.y, acc[0][1]);
        acc[0][2] = fmaf(a0, b.z, acc[0][2]); acc[0][3] = fmaf(a0, b.w, acc[0][3]);
        acc[1][0] = fmaf(a1, b.x, acc[1][0]); acc[1][1] = fmaf(a1, b.y, acc[1][1]);
        acc[1][2] = fmaf(a1, b.z, acc[1][2]); acc[1][3] = fmaf(a1, b.w, acc[1][3]);
        acc[2][0] = fmaf(a2, b.x, acc[2][0]); acc[2][1] = fmaf(a2, b.y, acc[2][1]);
        acc[2][2] = fmaf(a2, b.z, acc[2][2]); acc[2][3] = fmaf(a2, b.w, acc[2][3]);
        acc[3][0] = fmaf(a3, b.x, acc[3][0]); acc[3][1] = fmaf(a3, b.y, acc[3][1]);
        acc[3][2] = fmaf(a3, b.z, acc[3][2]); acc[3][3] = fmaf(a3, b.w, acc[3][3]);
    }

    #pragma unroll
    for (int i = 0; i < 4; i++) {
        int row = row0 + ty * 4 + i;
        if (row < n) {
            float4 o = make_float4(acc[i][0], acc[i][1], acc[i][2], acc[i][3]);
            *reinterpret_cast<float4*>(&out[(size_t)row * F_OUT + tx * 4]) = o;
        }
    }
}

// ---------------------------------------------------------------------------
extern "C" void kernel_launch(void* const* d_in, const int* in_sizes, int n_in,
                              void* d_out, int out_size) {
    const float* x  = (const float*)d_in[0];   // [100000, 65]
    const void*  ei = d_in[1];                 // [2, E] int64 or int32 (probed)
    const float* W1 = (const float*)d_in[2];   // [65, 64]
    const float* b1 = (const float*)d_in[3];   // [64]
    const float* W2 = (const float*)d_in[4];   // [64, 64]
    const float* b2 = (const float*)d_in[5];   // [64]
    float*       out = (float*)d_out;          // [100000, 64]

    int n_elems = in_sizes[1];
    int n_edges = n_elems / 2;
    if (n_edges > MAX_EDGES) n_edges = MAX_EDGES;

    // 1) zero counts + flag reset
    zero_cnt_kernel<<<(N_NODES + 255) / 256, 256>>>();

    // 2) sampled dtype probe
    int nprobe = n_elems / 2;
    if (nprobe > 65536) nprobe = 65536;
    detect_dtype_kernel<<<(nprobe + 255) / 256, 256>>>((const long long*)ei, nprobe);

    // 3) y = x @ W1
    int nblk = (N_NODES + 63) / 64;
    gemm1_kernel<<<nblk, 256>>>(x, W1, N_NODES);

    // 4) CSR build: histogram -> exclusive scan -> fill
    int eblk = (n_edges + 255) / 256;
    hist_kernel<<<eblk, 256>>>(ei, n_edges);
    chunk_sums_kernel<<<NCHUNKS, 256>>>();
    scan_bsums_kernel<<<1, 512>>>();
    scan_chunks_kernel<<<NCHUNKS, 256>>>();
    fill_kernel<<<eblk, 256>>>(ei, n_edges);

    // 5) aggregation + layer-1 epilogue: out = relu(y + b1 + sum y[src])
    int groups_per_block = 256 / 16;
    int ablk = (N_NODES + groups_per_block - 1) / groups_per_block;
    aggregate_kernel<<<ablk, 256>>>(b1, out, N_NODES);

    // 6) out = out @ W2 + b2   (in-place)
    gemm2_kernel<<<nblk, 256>>>(W2, b2, out, N_NODES);
}